// round 4
// baseline (speedup 1.0000x reference)
#include <cuda_runtime.h>
#include <cuda_bf16.h>
#include <cstdint>

// Problem constants
#define Nn   8
#define Cc   256
#define Hh   64
#define Ww   64
#define HWp  4096          // H*W
#define Gr   8             // groups
#define KK2  9             // K*K
#define GKK  72            // G*K*K
#define HIDc 256
#define HCc  16
#define NCHW (8*256*4096)
#define CSPLIT 4
#define CPB   (Cc/CSPLIT)            // 64 channels per block
#define NTILE 16                     // 4x4 tiles of 16x16
#define NBLK_MAIN (2*Nn*NTILE*CSPLIT)  // 1024

// ---------------- scratch (device globals: no allocation allowed) ----------------
__device__ float  g_gap[2][Nn][Cc];              // per-modality GAP
__device__ float  g_filt[2][Nn][GKK];            // softmaxed dynamic filters
__device__ float2 g_wAB[2][Nn][Cc];              // (wR - wT, wT) gating per channel
__device__ float  g_Fp[2][CSPLIT][Nn][HCc][HWp]; // partial 16-ch features (no bias)
__device__ float  g_bsum[NBLK_MAIN][HCc];        // per-block partial sums for Gf mean
__device__ float  g_wG[Nn][HCc];                 // global gate

// ---------------- Kernel 1: GAP over H,W (+ copy R to output) ----------------
__global__ void k_gap(const float* __restrict__ R, const float* __restrict__ T,
                      float* __restrict__ outR)
{
    int b   = blockIdx.x;          // 0..4095 : mod*2048 + (n*256+c)
    int mod = b >> 11;
    int nc  = b & 2047;
    const float4* p = (const float4*)((mod ? T : R) + (size_t)nc * HWp);
    float4* q = (mod == 0 && outR) ? (float4*)(outR + (size_t)nc * HWp) : nullptr;
    int t = threadIdx.x;           // 128 threads
    float s = 0.f;
#pragma unroll
    for (int i = 0; i < 8; i++) {
        float4 v = p[t + 128 * i];
        if (q) q[t + 128 * i] = v;
        s += v.x + v.y + v.z + v.w;
    }
#pragma unroll
    for (int o = 16; o; o >>= 1) s += __shfl_down_sync(0xffffffffu, s, o);
    __shared__ float sm[4];
    if ((t & 31) == 0) sm[t >> 5] = s;
    __syncthreads();
    if (t == 0)
        g_gap[mod][nc >> 8][nc & 255] = (sm[0] + sm[1] + sm[2] + sm[3]) * (1.f / 4096.f);
}

// ---------------- Kernel 2: per-sample filters + gating MLPs ----------------
__global__ void k_vec(const float* __restrict__ conv_w,
                      const float* __restrict__ bn_g, const float* __restrict__ bn_b,
                      const float* __restrict__ bn_m, const float* __restrict__ bn_v,
                      const float* __restrict__ f1W1, const float* __restrict__ f1b1,
                      const float* __restrict__ f1W2R, const float* __restrict__ f1b2R,
                      const float* __restrict__ f1W2T, const float* __restrict__ f1b2T,
                      const float* __restrict__ f2W1, const float* __restrict__ f2b1,
                      const float* __restrict__ f2W2R, const float* __restrict__ f2b2R,
                      const float* __restrict__ f2W2T, const float* __restrict__ f2b2T)
{
    int mod = blockIdx.x >> 3, n = blockIdx.x & 7;
    const float* W1  = mod ? f2W1  : f1W1;
    const float* b1  = mod ? f2b1  : f1b1;
    const float* W2R = mod ? f2W2R : f1W2R;
    const float* b2R = mod ? f2b2R : f1b2R;
    const float* W2T = mod ? f2W2T : f1W2T;
    const float* b2T = mod ? f2b2T : f1b2T;

    __shared__ float gp[Cc], hid[HIDc], lf[GKK];
    int t = threadIdx.x;   // 256
    gp[t] = g_gap[mod][n][t];
    __syncthreads();

    if (t < GKK) {         // dynamic filter logits + BN
        float a = 0.f;
        for (int i = 0; i < Cc; i++) a += gp[i] * conv_w[t * Cc + i];
        a = (a - bn_m[t]) * rsqrtf(bn_v[t] + 1e-5f) * bn_g[t] + bn_b[t];
        lf[t] = a;
    }
    float a = b1[t];       // hidden layer (uses gap directly: (fl+fh).mean == gap)
    for (int i = 0; i < Cc; i++) a += gp[i] * W1[i * HIDc + t];
    hid[t] = fmaxf(a, 0.f);
    __syncthreads();

    if (t < Gr) {          // softmax over each group of 9
        float mx = -1e30f;
#pragma unroll
        for (int k = 0; k < KK2; k++) mx = fmaxf(mx, lf[t * KK2 + k]);
        float e[KK2], sum = 0.f;
#pragma unroll
        for (int k = 0; k < KK2; k++) { e[k] = expf(lf[t * KK2 + k] - mx); sum += e[k]; }
        float inv = 1.f / sum;
#pragma unroll
        for (int k = 0; k < KK2; k++) g_filt[mod][n][t * KK2 + k] = e[k] * inv;
    }
    float aR = b2R[t], aT = b2T[t];
    for (int i = 0; i < HIDc; i++) {
        float h = hid[i];
        aR += h * W2R[i * Cc + t];
        aT += h * W2T[i * Cc + t];
    }
    float wR = 1.f / (1.f + expf(-aR));
    float wT = 1.f / (1.f + expf(-aT));
    g_wAB[mod][n][t] = make_float2(wR - wT, wT);
}

// ---------------- Kernel 3: involution + gating + 256->16 conv (fused, split-C) ----
// grid = 1024: (((mod*8 + n)*16 + tile)*4 + cs); tile: 4x4 of 16x16 pixels;
// cs selects 64 channels. 256 threads, 1 pixel/thread (16 accumulators -> no
// spills). 4 halo buffers, 2 channels per __syncthreads.
#define HSTR 20
__global__ void __launch_bounds__(256, 3) k_main(const float* __restrict__ R,
                                                 const float* __restrict__ T,
                                                 const float* __restrict__ fv_wR,
                                                 const float* __restrict__ fv_wT)
{
    int b    = blockIdx.x;
    int cs   = b & 3;
    int r    = b >> 2;
    int tile = r & 15;
    r >>= 4;
    int n    = r & 7;
    int mod  = r >> 3;
    int ty0 = (tile >> 2) * 16;
    int tx0 = (tile & 3) * 16;

    const float* X    = (mod ? T : R) + (size_t)n * Cc * HWp + (size_t)cs * CPB * HWp;
    const float* wmat = mod ? fv_wT : fv_wR;      // [16][256]
    float* Out = &g_Fp[mod][cs][n][0][0];

    __shared__ float  buf[4][18 * HSTR];
    __shared__ float  wv[CPB * HCc];       // transposed: wv[c*16+o], c local
    __shared__ float2 ab_sm[CPB];
    __shared__ float  filt_sm[2 * KK2];    // 2 groups per split
    __shared__ float  red[8][HCc];

    int t = threadIdx.x;
    for (int i = t; i < CPB * HCc; i += 256) {
        int o = i >> 6, c = i & 63;
        wv[c * HCc + o] = wmat[o * Cc + cs * CPB + c];
    }
    if (t < CPB) ab_sm[t] = g_wAB[mod][n][cs * CPB + t];
    if (t < 2 * KK2) filt_sm[t] = g_filt[mod][n][cs * 2 * KK2 + t];

    // halo mapping: 18x18 = 324 loads, 256 threads -> 2 slots
    int rr0 = t / 18, qq0 = t - rr0 * 18;
    int gy0 = ty0 - 1 + rr0; gy0 = gy0 < 0 ? -gy0 : (gy0 > 63 ? 126 - gy0 : gy0);
    int gx0 = tx0 - 1 + qq0; gx0 = gx0 < 0 ? -gx0 : (gx0 > 63 ? 126 - gx0 : gx0);
    int goff0 = gy0 * Ww + gx0, soff0 = rr0 * HSTR + qq0;
    int  idx1 = t + 256;
    bool has1 = idx1 < 324;
    int rr1 = has1 ? idx1 / 18 : 0, qq1 = idx1 - rr1 * 18;
    if (!has1) qq1 = 0;
    int gy1 = ty0 - 1 + rr1; gy1 = gy1 < 0 ? -gy1 : (gy1 > 63 ? 126 - gy1 : gy1);
    int gx1 = tx0 - 1 + qq1; gx1 = gx1 < 0 ? -gx1 : (gx1 > 63 ? 126 - gx1 : gx1);
    int goff1 = gy1 * Ww + gx1, soff1 = rr1 * HSTR + qq1;

    int tx = t & 15, ly = t >> 4;
    int base = ly * HSTR + tx;

    float acc[HCc];
#pragma unroll
    for (int i = 0; i < HCc; i++) acc[i] = 0.f;

    {   // preload channels 0,1 of this split
        const float* X0 = X;
        const float* X1 = X + HWp;
        buf[0][soff0] = X0[goff0];
        buf[1][soff0] = X1[goff0];
        if (has1) { buf[0][soff1] = X0[goff1]; buf[1][soff1] = X1[goff1]; }
    }
    __syncthreads();

    float f[KK2];
    for (int pi = 0; pi < CPB / 2; pi++) {
        int cur = (pi & 1) * 2;
        if (pi + 1 < CPB / 2) {
            int nb = cur ^ 2;
            const float* Xa = X + (size_t)(2 * pi + 2) * HWp;
            const float* Xb = X + (size_t)(2 * pi + 3) * HWp;
            buf[nb][soff0]     = Xa[goff0];
            buf[nb + 1][soff0] = Xb[goff0];
            if (has1) { buf[nb][soff1] = Xa[goff1]; buf[nb + 1][soff1] = Xb[goff1]; }
        }
        if ((pi & 15) == 0) {
            int gl = pi >> 4;   // group-local: 0 or 1
#pragma unroll
            for (int k = 0; k < KK2; k++) f[k] = filt_sm[gl * KK2 + k];
        }
#pragma unroll
        for (int s = 0; s < 2; s++) {
            int c = 2 * pi + s;
            float2 ab = ab_sm[c];
            const float* Bp = &buf[cur + s][base];
            float v00 = Bp[0],        v01 = Bp[1],            v02 = Bp[2];
            float v10 = Bp[HSTR],     v11 = Bp[HSTR + 1],     v12 = Bp[HSTR + 2];
            float v20 = Bp[2 * HSTR], v21 = Bp[2 * HSTR + 1], v22 = Bp[2 * HSTR + 2];
            float low = f[0]*v00 + f[1]*v01 + f[2]*v02
                      + f[3]*v10 + f[4]*v11 + f[5]*v12
                      + f[6]*v20 + f[7]*v21 + f[8]*v22;
            float val = ab.y * v11 + ab.x * low;    // wT*X + (wR-wT)*low
            const float4* wp = (const float4*)&wv[c * HCc];
#pragma unroll
            for (int q = 0; q < 4; q++) {
                float4 w = wp[q];
                acc[q*4+0] += w.x * val; acc[q*4+1] += w.y * val;
                acc[q*4+2] += w.z * val; acc[q*4+3] += w.w * val;
            }
        }
        __syncthreads();
    }

    // store partial outputs (no bias)
    int y = ty0 + ly, x = tx0 + tx;
#pragma unroll
    for (int hc = 0; hc < HCc; hc++)
        Out[hc * HWp + y * Ww + x] = acc[hc];

    // deterministic per-block reduction of tile sums for the Gf-mean path
    int lane = t & 31, w = t >> 5;
#pragma unroll
    for (int hc = 0; hc < HCc; hc++) {
        float v = acc[hc];
#pragma unroll
        for (int o = 16; o; o >>= 1) v += __shfl_down_sync(0xffffffffu, v, o);
        if (lane == 0) red[w][hc] = v;
    }
    __syncthreads();
    if (t < HCc) {
        float s = 0.f;
#pragma unroll
        for (int ww = 0; ww < 8; ww++) s += red[ww][t];
        g_bsum[blockIdx.x][t] = s;
    }
}

// ---------------- Kernel 4: tiny Gf-mean gate ----------------
__global__ void k_wg2(const float* __restrict__ Lw, const float* __restrict__ Lb,
                      const float* __restrict__ bR, const float* __restrict__ bT)
{
    __shared__ float mean[Nn * HCc];
    int t = threadIdx.x;   // 128 : n*16 + hc
    int n = t >> 4, hc = t & 15;
    float s = 0.f;
#pragma unroll 2
    for (int mod = 0; mod < 2; mod++)
        for (int tile = 0; tile < NTILE; tile++)
            for (int cs = 0; cs < CSPLIT; cs++) {
                int idx = (((mod * Nn + n) * NTILE + tile) << 2) + cs;
                s += g_bsum[idx][hc];
            }
    mean[t] = s * (1.f / 4096.f) + bR[hc] + bT[hc];
    __syncthreads();
    float a = Lb[hc];
#pragma unroll
    for (int i = 0; i < HCc; i++) a += mean[n * HCc + i] * Lw[i * HCc + hc];
    g_wG[n][hc] = 1.f / (1.f + expf(-a));
}

// ---------------- Kernel 5: fovea softmax (over W) + 16->256 conv ----------------
__global__ void __launch_bounds__(256) k_out(const float* __restrict__ wO,
                                             const float* __restrict__ bO,
                                             const float* __restrict__ sRp,
                                             const float* __restrict__ sTp,
                                             const float* __restrict__ bR,
                                             const float* __restrict__ bT,
                                             float* __restrict__ out)
{
    int b = blockIdx.x;            // 512: n*64 + y
    int n = b >> 6, y = b & 63;
    __shared__ float  sR[HCc * Ww], sT[HCc * Ww], fu[HCc * Ww];
    __shared__ float4 wo[Cc * 4];  // wO rows as float4: wo[co*4+q]
    __shared__ float  bo[Cc];
    int t = threadIdx.x;

#pragma unroll
    for (int i = t; i < HCc * Ww; i += 256) {
        int hc = i >> 6, x = i & 63;
        int off = hc * HWp + y * Ww + x;
        float r = bR[hc], tv = bT[hc];
#pragma unroll
        for (int cs = 0; cs < CSPLIT; cs++) {
            r  += g_Fp[0][cs][n][0][off];
            tv += g_Fp[1][cs][n][0][off];
        }
        sR[i] = r;
        sT[i] = tv;
    }
    for (int i = t; i < Cc * 4; i += 256) wo[i] = ((const float4*)wO)[i];
    bo[t] = bO[t];
    float scR = sRp[0], scT = sTp[0];
    __syncthreads();

    int lane = t & 31, w = t >> 5;
#pragma unroll
    for (int hh = 0; hh < 2; hh++) {
        int hc = w + hh * 8;
        float rf0 = sR[hc * Ww + lane], rf1 = sR[hc * Ww + lane + 32];
        float tf0 = sT[hc * Ww + lane], tf1 = sT[hc * Ww + lane + 32];
        float a0 = rf0 * scR, a1 = rf1 * scR;
        float m = fmaxf(a0, a1);
#pragma unroll
        for (int o = 16; o; o >>= 1) m = fmaxf(m, __shfl_xor_sync(0xffffffffu, m, o));
        float e0 = expf(a0 - m), e1 = expf(a1 - m);
        float s = e0 + e1;
#pragma unroll
        for (int o = 16; o; o >>= 1) s += __shfl_xor_sync(0xffffffffu, s, o);
        float inv = 1.f / s;
        float mR0 = e0 * inv, mR1 = e1 * inv;
        float c0 = tf0 * scT, c1 = tf1 * scT;
        float mt = fmaxf(c0, c1);
#pragma unroll
        for (int o = 16; o; o >>= 1) mt = fmaxf(mt, __shfl_xor_sync(0xffffffffu, mt, o));
        float g0 = expf(c0 - mt), g1 = expf(c1 - mt);
        float st = g0 + g1;
#pragma unroll
        for (int o = 16; o; o >>= 1) st += __shfl_xor_sync(0xffffffffu, st, o);
        float invt = 1.f / st;
        float mT0 = g0 * invt, mT1 = g1 * invt;

        float wg = g_wG[n][hc];
        fu[hc * Ww + lane]      = mR0 * rf0 + mT0 * tf0 + wg * (rf0 + tf0);
        fu[hc * Ww + lane + 32] = mR1 * rf1 + mT1 * tf1 + wg * (rf1 + tf1);
    }
    __syncthreads();

    int x = t & 63, co0 = t >> 6;
    float fx[HCc];
#pragma unroll
    for (int i = 0; i < HCc; i++) fx[i] = fu[i * Ww + x];
    float* outp = out + (size_t)n * Cc * HWp + y * Ww + x;
    for (int co = co0; co < Cc; co += 4) {
        const float4* wp = &wo[co * 4];
        float a = bo[co];
#pragma unroll
        for (int q = 0; q < 4; q++) {
            float4 ww = wp[q];
            a += ww.x * fx[q*4+0] + ww.y * fx[q*4+1] + ww.z * fx[q*4+2] + ww.w * fx[q*4+3];
        }
        outp[(size_t)co * HWp] = a;
    }
}

// ---------------- launch ----------------
extern "C" void kernel_launch(void* const* d_in, const int* in_sizes, int n_in,
                              void* d_out, int out_size)
{
    const float* R      = (const float*)d_in[0];
    const float* T      = (const float*)d_in[1];
    const float* conv_w = (const float*)d_in[2];
    const float* bn_g   = (const float*)d_in[3];
    const float* bn_b   = (const float*)d_in[4];
    const float* bn_m   = (const float*)d_in[5];
    const float* bn_v   = (const float*)d_in[6];
    const float* f1W1   = (const float*)d_in[7];
    const float* f1b1   = (const float*)d_in[8];
    const float* f1W2R  = (const float*)d_in[9];
    const float* f1b2R  = (const float*)d_in[10];
    const float* f1W2T  = (const float*)d_in[11];
    const float* f1b2T  = (const float*)d_in[12];
    const float* f2W1   = (const float*)d_in[13];
    const float* f2b1   = (const float*)d_in[14];
    const float* f2W2R  = (const float*)d_in[15];
    const float* f2b2R  = (const float*)d_in[16];
    const float* f2W2T  = (const float*)d_in[17];
    const float* f2b2T  = (const float*)d_in[18];
    const float* fv_wR  = (const float*)d_in[19];
    const float* fv_bR  = (const float*)d_in[20];
    const float* fv_wT  = (const float*)d_in[21];
    const float* fv_bT  = (const float*)d_in[22];
    const float* fv_Lw  = (const float*)d_in[23];
    const float* fv_Lb  = (const float*)d_in[24];
    const float* fv_wO  = (const float*)d_in[25];
    const float* fv_bO  = (const float*)d_in[26];
    const float* fv_sR  = (const float*)d_in[27];
    const float* fv_sT  = (const float*)d_in[28];

    float* out  = (float*)d_out;
    float* outR = nullptr;
    float* outO = out;
    if (out_size >= 2 * NCHW) {   // output is (R, out) concatenated
        outR = out;
        outO = out + NCHW;
    }

    k_gap<<<4096, 128>>>(R, T, outR);
    k_vec<<<16, 256>>>(conv_w, bn_g, bn_b, bn_m, bn_v,
                       f1W1, f1b1, f1W2R, f1b2R, f1W2T, f1b2T,
                       f2W1, f2b1, f2W2R, f2b2R, f2W2T, f2b2T);
    k_main<<<NBLK_MAIN, 256>>>(R, T, fv_wR, fv_wT);
    k_wg2<<<1, 128>>>(fv_Lw, fv_Lb, fv_bR, fv_bT);
    k_out<<<512, 256>>>(fv_wO, fv_bO, fv_sR, fv_sT, fv_bR, fv_bT, outO);
}

// round 5
// speedup vs baseline: 1.2969x; 1.2969x over previous
#include <cuda_runtime.h>
#include <cuda_bf16.h>
#include <cuda_pipeline.h>
#include <cstdint>

// Problem constants
#define Nn   8
#define Cc   256
#define Hh   64
#define Ww   64
#define HWp  4096          // H*W
#define Gr   8             // groups
#define KK2  9             // K*K
#define GKK  72            // G*K*K
#define HIDc 256
#define HCc  16
#define NCHW (8*256*4096)
#define CSPLIT 4
#define CPB   (Cc/CSPLIT)            // 64 channels per block
#define NTILE 16                     // 4x4 tiles of 16x16
#define NBLK_MAIN (2*Nn*NTILE*CSPLIT)  // 1024

// ---------------- scratch (device globals: no allocation allowed) ----------------
__device__ float  g_gap[2][Nn][Cc];              // per-modality GAP
__device__ float  g_hid[2][Nn][HIDc];            // MLP hidden activations
__device__ float  g_filt[2][Nn][GKK];            // softmaxed dynamic filters
__device__ float2 g_wAB[2][Nn][Cc];              // (wR - wT, wT) gating per channel
__device__ float  g_Fp[2][CSPLIT][Nn][HCc][HWp]; // partial 16-ch features (no bias)
__device__ float  g_bsum[NBLK_MAIN][HCc];        // per-block partial sums for Gf mean
__device__ float  g_wG[Nn][HCc];                 // global gate

// ---------------- Kernel 1: GAP over H,W (+ copy R to output) ----------------
__global__ void k_gap(const float* __restrict__ R, const float* __restrict__ T,
                      float* __restrict__ outR)
{
    int b   = blockIdx.x;          // 0..4095 : mod*2048 + (n*256+c)
    int mod = b >> 11;
    int nc  = b & 2047;
    const float4* p = (const float4*)((mod ? T : R) + (size_t)nc * HWp);
    float4* q = (mod == 0 && outR) ? (float4*)(outR + (size_t)nc * HWp) : nullptr;
    int t = threadIdx.x;           // 128 threads
    float s = 0.f;
#pragma unroll
    for (int i = 0; i < 8; i++) {
        float4 v = p[t + 128 * i];
        if (q) q[t + 128 * i] = v;
        s += v.x + v.y + v.z + v.w;
    }
#pragma unroll
    for (int o = 16; o; o >>= 1) s += __shfl_down_sync(0xffffffffu, s, o);
    __shared__ float sm[4];
    if ((t & 31) == 0) sm[t >> 5] = s;
    __syncthreads();
    if (t == 0)
        g_gap[mod][nc >> 8][nc & 255] = (sm[0] + sm[1] + sm[2] + sm[3]) * (1.f / 4096.f);
}

// ---------------- Kernel 2a: hidden layer + dynamic filters ----------------
// grid = 2*8*9 = 144.  j<8: 32 hidden outputs each (warp-split over i).
// j==8: all 72 filter logits (+BN+softmax).
__global__ void k_vecA(const float* __restrict__ conv_w,
                       const float* __restrict__ bn_g, const float* __restrict__ bn_b,
                       const float* __restrict__ bn_m, const float* __restrict__ bn_v,
                       const float* __restrict__ f1W1, const float* __restrict__ f1b1,
                       const float* __restrict__ f2W1, const float* __restrict__ f2b1)
{
    int b = blockIdx.x;
    int j = b % 9;
    int n = (b / 9) & 7;
    int mod = b / 72;
    const float* W1 = mod ? f2W1 : f1W1;
    const float* b1 = mod ? f2b1 : f1b1;

    __shared__ float gp[Cc];
    __shared__ float part[8][32];
    __shared__ float lf_sm[GKK];
    int t = threadIdx.x;          // 256
    gp[t] = g_gap[mod][n][t];
    __syncthreads();

    int lane = t & 31, w = t >> 5;
    if (j < 8) {
        int o = j * 32 + lane;
        const float* Wp = W1 + (size_t)(w * 32) * HIDc + o;
        float s = 0.f;
#pragma unroll
        for (int i = 0; i < 32; i++) s += gp[w * 32 + i] * Wp[(size_t)i * HIDc];
        part[w][lane] = s;
        __syncthreads();
        if (t < 32) {
            float a = b1[j * 32 + t];
#pragma unroll
            for (int ww = 0; ww < 8; ww++) a += part[ww][t];
            g_hid[mod][n][j * 32 + t] = fmaxf(a, 0.f);
        }
    } else {
        // filter logits: warp w -> outputs w*9 .. w*9+8
#pragma unroll
        for (int k = 0; k < KK2; k++) {
            int o = w * KK2 + k;
            const float* cw = conv_w + (size_t)o * Cc;
            float a = 0.f;
#pragma unroll
            for (int q = 0; q < 8; q++) a += gp[lane + 32 * q] * cw[lane + 32 * q];
#pragma unroll
            for (int off = 16; off; off >>= 1) a += __shfl_down_sync(0xffffffffu, a, off);
            if (lane == 0)
                lf_sm[o] = (a - bn_m[o]) * rsqrtf(bn_v[o] + 1e-5f) * bn_g[o] + bn_b[o];
        }
        __syncthreads();
        if (t < Gr) {
            float mx = -1e30f;
#pragma unroll
            for (int k = 0; k < KK2; k++) mx = fmaxf(mx, lf_sm[t * KK2 + k]);
            float e[KK2], sum = 0.f;
#pragma unroll
            for (int k = 0; k < KK2; k++) { e[k] = expf(lf_sm[t * KK2 + k] - mx); sum += e[k]; }
            float inv = 1.f / sum;
#pragma unroll
            for (int k = 0; k < KK2; k++) g_filt[mod][n][t * KK2 + k] = e[k] * inv;
        }
    }
}

// ---------------- Kernel 2b: sigmoid gating layers ----------------
// grid = 2*8*2 = 32 : (mod, n, half of 128 outputs). Warp-split over i.
__global__ void k_vecB(const float* __restrict__ f1W2R, const float* __restrict__ f1b2R,
                       const float* __restrict__ f1W2T, const float* __restrict__ f1b2T,
                       const float* __restrict__ f2W2R, const float* __restrict__ f2b2R,
                       const float* __restrict__ f2W2T, const float* __restrict__ f2b2T)
{
    int b = blockIdx.x;
    int half = b & 1;
    int n = (b >> 1) & 7;
    int mod = b >> 4;
    const float* W2R = mod ? f2W2R : f1W2R;
    const float* b2R = mod ? f2b2R : f1b2R;
    const float* W2T = mod ? f2W2T : f1W2T;
    const float* b2T = mod ? f2b2T : f1b2T;

    __shared__ float hid_sm[HIDc];
    __shared__ float psR[8][128], psT[8][128];
    int t = threadIdx.x;          // 256
    hid_sm[t] = g_hid[mod][n][t];
    __syncthreads();

    int lane = t & 31, w = t >> 5;
#pragma unroll
    for (int ch = 0; ch < 4; ch++) {
        int o = half * 128 + ch * 32 + lane;
        float aR = 0.f, aT = 0.f;
#pragma unroll
        for (int i2 = 0; i2 < 32; i2++) {
            float h = hid_sm[w * 32 + i2];
            size_t idx = (size_t)(w * 32 + i2) * Cc + o;
            aR += h * W2R[idx];
            aT += h * W2T[idx];
        }
        psR[w][ch * 32 + lane] = aR;
        psT[w][ch * 32 + lane] = aT;
    }
    __syncthreads();
    if (t < 128) {
        int o = half * 128 + t;
        float aR = b2R[o], aT = b2T[o];
#pragma unroll
        for (int ww = 0; ww < 8; ww++) { aR += psR[ww][t]; aT += psT[ww][t]; }
        float wR = 1.f / (1.f + expf(-aR));
        float wT = 1.f / (1.f + expf(-aT));
        g_wAB[mod][n][o] = make_float2(wR - wT, wT);
    }
}

// ---------------- Kernel 3: involution + gating + 256->16 conv (fused, split-C) ----
// grid = 1024: (((mod*8 + n)*16 + tile)*4 + cs); tile: 4x4 of 16x16 pixels;
// cs selects 64 channels. 256 threads, 1 pixel/thread. cp.async pipeline,
// 8 channel buffers, lookahead 3 phases (2 channels/phase).
#define HSTR 20
#define NPH  (CPB/2)   // 32 phases
__global__ void __launch_bounds__(256) k_main(const float* __restrict__ R,
                                              const float* __restrict__ T,
                                              const float* __restrict__ fv_wR,
                                              const float* __restrict__ fv_wT)
{
    int b    = blockIdx.x;
    int cs   = b & 3;
    int r    = b >> 2;
    int tile = r & 15;
    r >>= 4;
    int n    = r & 7;
    int mod  = r >> 3;
    int ty0 = (tile >> 2) * 16;
    int tx0 = (tile & 3) * 16;

    const float* X    = (mod ? T : R) + (size_t)n * Cc * HWp + (size_t)cs * CPB * HWp;
    const float* wmat = mod ? fv_wT : fv_wR;      // [16][256]
    float* Out = &g_Fp[mod][cs][n][0][0];

    __shared__ float  buf[8][18 * HSTR];
    __shared__ float  wv[CPB * HCc];       // transposed: wv[c*16+o], c local
    __shared__ float2 ab_sm[CPB];
    __shared__ float  filt_sm[2 * KK2];    // 2 groups per split
    __shared__ float  red[8][HCc];

    int t = threadIdx.x;
    for (int i = t; i < CPB * HCc; i += 256) {
        int o = i >> 6, c = i & 63;
        wv[c * HCc + o] = wmat[o * Cc + cs * CPB + c];
    }
    if (t < CPB) ab_sm[t] = g_wAB[mod][n][cs * CPB + t];
    if (t < 2 * KK2) filt_sm[t] = g_filt[mod][n][cs * 2 * KK2 + t];

    // halo mapping: 18x18 = 324 loads, 256 threads -> <=2 slots each
    int rr0 = t / 18, qq0 = t - rr0 * 18;
    int gy0 = ty0 - 1 + rr0; gy0 = gy0 < 0 ? -gy0 : (gy0 > 63 ? 126 - gy0 : gy0);
    int gx0 = tx0 - 1 + qq0; gx0 = gx0 < 0 ? -gx0 : (gx0 > 63 ? 126 - gx0 : gx0);
    int goff0 = gy0 * Ww + gx0, soff0 = rr0 * HSTR + qq0;
    int  idx1 = t + 256;
    bool has1 = idx1 < 324;
    int rr1 = has1 ? idx1 / 18 : 0, qq1 = idx1 - rr1 * 18;
    if (!has1) qq1 = 0;
    int gy1 = ty0 - 1 + rr1; gy1 = gy1 < 0 ? -gy1 : (gy1 > 63 ? 126 - gy1 : gy1);
    int gx1 = tx0 - 1 + qq1; gx1 = gx1 < 0 ? -gx1 : (gx1 > 63 ? 126 - gx1 : gx1);
    int goff1 = gy1 * Ww + gx1, soff1 = rr1 * HSTR + qq1;

    int tx = t & 15, ly = t >> 4;
    int base = ly * HSTR + tx;

    float acc[HCc];
#pragma unroll
    for (int i = 0; i < HCc; i++) acc[i] = 0.f;

    // pipeline prologue: issue phases 0,1,2
#pragma unroll
    for (int p = 0; p < 3; p++) {
        int c0 = 2 * p;
        const float* Xa = X + (size_t)c0 * HWp;
        const float* Xb = Xa + HWp;
        float* Ba = buf[c0 & 7];
        float* Bb = buf[(c0 + 1) & 7];
        __pipeline_memcpy_async(&Ba[soff0], &Xa[goff0], 4);
        __pipeline_memcpy_async(&Bb[soff0], &Xb[goff0], 4);
        if (has1) {
            __pipeline_memcpy_async(&Ba[soff1], &Xa[goff1], 4);
            __pipeline_memcpy_async(&Bb[soff1], &Xb[goff1], 4);
        }
        __pipeline_commit();
    }

    float f[KK2];
    for (int p = 0; p < NPH; p++) {
        {   // issue phase p+3
            int q = p + 3;
            if (q < NPH) {
                int c0 = 2 * q;
                const float* Xa = X + (size_t)c0 * HWp;
                const float* Xb = Xa + HWp;
                float* Ba = buf[c0 & 7];
                float* Bb = buf[(c0 + 1) & 7];
                __pipeline_memcpy_async(&Ba[soff0], &Xa[goff0], 4);
                __pipeline_memcpy_async(&Bb[soff0], &Xb[goff0], 4);
                if (has1) {
                    __pipeline_memcpy_async(&Ba[soff1], &Xa[goff1], 4);
                    __pipeline_memcpy_async(&Bb[soff1], &Xb[goff1], 4);
                }
            }
            __pipeline_commit();
        }
        __pipeline_wait_prior(3);   // phase p's own loads complete
        __syncthreads();            // all threads' loads visible

        if ((p & 15) == 0) {
            int gl = p >> 4;   // group-local: 0 or 1
#pragma unroll
            for (int k = 0; k < KK2; k++) f[k] = filt_sm[gl * KK2 + k];
        }
#pragma unroll
        for (int s = 0; s < 2; s++) {
            int c = 2 * p + s;
            float2 ab = ab_sm[c];
            const float* Bp = &buf[c & 7][base];
            float v00 = Bp[0],        v01 = Bp[1],            v02 = Bp[2];
            float v10 = Bp[HSTR],     v11 = Bp[HSTR + 1],     v12 = Bp[HSTR + 2];
            float v20 = Bp[2 * HSTR], v21 = Bp[2 * HSTR + 1], v22 = Bp[2 * HSTR + 2];
            float low = f[0]*v00 + f[1]*v01 + f[2]*v02
                      + f[3]*v10 + f[4]*v11 + f[5]*v12
                      + f[6]*v20 + f[7]*v21 + f[8]*v22;
            float val = ab.y * v11 + ab.x * low;    // wT*X + (wR-wT)*low
            const float4* wp = (const float4*)&wv[c * HCc];
#pragma unroll
            for (int q = 0; q < 4; q++) {
                float4 w = wp[q];
                acc[q*4+0] += w.x * val; acc[q*4+1] += w.y * val;
                acc[q*4+2] += w.z * val; acc[q*4+3] += w.w * val;
            }
        }
        __syncthreads();   // buffers reused by phase p+4's issue next iteration
    }

    // store partial outputs (no bias)
    int y = ty0 + ly, x = tx0 + tx;
#pragma unroll
    for (int hc = 0; hc < HCc; hc++)
        Out[hc * HWp + y * Ww + x] = acc[hc];

    // deterministic per-block reduction of tile sums for the Gf-mean path
    int lane = t & 31, w = t >> 5;
#pragma unroll
    for (int hc = 0; hc < HCc; hc++) {
        float v = acc[hc];
#pragma unroll
        for (int o = 16; o; o >>= 1) v += __shfl_down_sync(0xffffffffu, v, o);
        if (lane == 0) red[w][hc] = v;
    }
    __syncthreads();
    if (t < HCc) {
        float s = 0.f;
#pragma unroll
        for (int ww = 0; ww < 8; ww++) s += red[ww][t];
        g_bsum[blockIdx.x][t] = s;
    }
}

// ---------------- Kernel 4: Gf-mean gate (grid = 8) ----------------
__global__ void k_wg3(const float* __restrict__ Lw, const float* __restrict__ Lb,
                      const float* __restrict__ bR, const float* __restrict__ bT)
{
    int n = blockIdx.x;
    int t = threadIdx.x;          // 256 : slice = t>>4 (16), hc = t&15
    int hc = t & 15, sl = t >> 4;
    __shared__ float red2[16][17];
    __shared__ float mean[HCc];
    float s = 0.f;
#pragma unroll
    for (int k = 0; k < 8; k++) {
        int rr = sl * 8 + k;               // 0..127 : mod*64 + tile*4 + cs
        int idx = ((rr >> 6) * 8 + n) * 64 + (rr & 63);
        s += g_bsum[idx][hc];
    }
    red2[sl][hc] = s;
    __syncthreads();
    if (t < HCc) {
        float a = 0.f;
#pragma unroll
        for (int k = 0; k < 16; k++) a += red2[k][t];
        mean[t] = a * (1.f / 4096.f) + bR[t] + bT[t];
    }
    __syncthreads();
    if (t < HCc) {
        float a = Lb[t];
#pragma unroll
        for (int i = 0; i < HCc; i++) a += mean[i] * Lw[i * HCc + t];
        g_wG[n][t] = 1.f / (1.f + expf(-a));
    }
}

// ---------------- Kernel 5: fovea softmax (over W) + 16->256 conv ----------------
__global__ void __launch_bounds__(256) k_out(const float* __restrict__ wO,
                                             const float* __restrict__ bO,
                                             const float* __restrict__ sRp,
                                             const float* __restrict__ sTp,
                                             const float* __restrict__ bR,
                                             const float* __restrict__ bT,
                                             float* __restrict__ out)
{
    int b = blockIdx.x;            // 512: n*64 + y
    int n = b >> 6, y = b & 63;
    __shared__ float  sR[HCc * Ww], sT[HCc * Ww], fu[HCc * Ww];
    __shared__ float4 wo[Cc * 4];  // wO rows as float4: wo[co*4+q]
    __shared__ float  bo[Cc];
    int t = threadIdx.x;

#pragma unroll
    for (int i = t; i < HCc * Ww; i += 256) {
        int hc = i >> 6, x = i & 63;
        int off = hc * HWp + y * Ww + x;
        float r = bR[hc], tv = bT[hc];
#pragma unroll
        for (int cs = 0; cs < CSPLIT; cs++) {
            r  += g_Fp[0][cs][n][0][off];
            tv += g_Fp[1][cs][n][0][off];
        }
        sR[i] = r;
        sT[i] = tv;
    }
    for (int i = t; i < Cc * 4; i += 256) wo[i] = ((const float4*)wO)[i];
    bo[t] = bO[t];
    float scR = sRp[0], scT = sTp[0];
    __syncthreads();

    int lane = t & 31, w = t >> 5;
#pragma unroll
    for (int hh = 0; hh < 2; hh++) {
        int hc = w + hh * 8;
        float rf0 = sR[hc * Ww + lane], rf1 = sR[hc * Ww + lane + 32];
        float tf0 = sT[hc * Ww + lane], tf1 = sT[hc * Ww + lane + 32];
        float a0 = rf0 * scR, a1 = rf1 * scR;
        float m = fmaxf(a0, a1);
#pragma unroll
        for (int o = 16; o; o >>= 1) m = fmaxf(m, __shfl_xor_sync(0xffffffffu, m, o));
        float e0 = expf(a0 - m), e1 = expf(a1 - m);
        float s = e0 + e1;
#pragma unroll
        for (int o = 16; o; o >>= 1) s += __shfl_xor_sync(0xffffffffu, s, o);
        float inv = 1.f / s;
        float mR0 = e0 * inv, mR1 = e1 * inv;
        float c0 = tf0 * scT, c1 = tf1 * scT;
        float mt = fmaxf(c0, c1);
#pragma unroll
        for (int o = 16; o; o >>= 1) mt = fmaxf(mt, __shfl_xor_sync(0xffffffffu, mt, o));
        float g0 = expf(c0 - mt), g1 = expf(c1 - mt);
        float st = g0 + g1;
#pragma unroll
        for (int o = 16; o; o >>= 1) st += __shfl_xor_sync(0xffffffffu, st, o);
        float invt = 1.f / st;
        float mT0 = g0 * invt, mT1 = g1 * invt;

        float wg = g_wG[n][hc];
        fu[hc * Ww + lane]      = mR0 * rf0 + mT0 * tf0 + wg * (rf0 + tf0);
        fu[hc * Ww + lane + 32] = mR1 * rf1 + mT1 * tf1 + wg * (rf1 + tf1);
    }
    __syncthreads();

    int x = t & 63, co0 = t >> 6;
    float fx[HCc];
#pragma unroll
    for (int i = 0; i < HCc; i++) fx[i] = fu[i * Ww + x];
    float* outp = out + (size_t)n * Cc * HWp + y * Ww + x;
    for (int co = co0; co < Cc; co += 4) {
        const float4* wp = &wo[co * 4];
        float a = bo[co];
#pragma unroll
        for (int q = 0; q < 4; q++) {
            float4 ww = wp[q];
            a += ww.x * fx[q*4+0] + ww.y * fx[q*4+1] + ww.z * fx[q*4+2] + ww.w * fx[q*4+3];
        }
        outp[(size_t)co * HWp] = a;
    }
}

// ---------------- launch ----------------
extern "C" void kernel_launch(void* const* d_in, const int* in_sizes, int n_in,
                              void* d_out, int out_size)
{
    const float* R      = (const float*)d_in[0];
    const float* T      = (const float*)d_in[1];
    const float* conv_w = (const float*)d_in[2];
    const float* bn_g   = (const float*)d_in[3];
    const float* bn_b   = (const float*)d_in[4];
    const float* bn_m   = (const float*)d_in[5];
    const float* bn_v   = (const float*)d_in[6];
    const float* f1W1   = (const float*)d_in[7];
    const float* f1b1   = (const float*)d_in[8];
    const float* f1W2R  = (const float*)d_in[9];
    const float* f1b2R  = (const float*)d_in[10];
    const float* f1W2T  = (const float*)d_in[11];
    const float* f1b2T  = (const float*)d_in[12];
    const float* f2W1   = (const float*)d_in[13];
    const float* f2b1   = (const float*)d_in[14];
    const float* f2W2R  = (const float*)d_in[15];
    const float* f2b2R  = (const float*)d_in[16];
    const float* f2W2T  = (const float*)d_in[17];
    const float* f2b2T  = (const float*)d_in[18];
    const float* fv_wR  = (const float*)d_in[19];
    const float* fv_bR  = (const float*)d_in[20];
    const float* fv_wT  = (const float*)d_in[21];
    const float* fv_bT  = (const float*)d_in[22];
    const float* fv_Lw  = (const float*)d_in[23];
    const float* fv_Lb  = (const float*)d_in[24];
    const float* fv_wO  = (const float*)d_in[25];
    const float* fv_bO  = (const float*)d_in[26];
    const float* fv_sR  = (const float*)d_in[27];
    const float* fv_sT  = (const float*)d_in[28];

    float* out  = (float*)d_out;
    float* outR = nullptr;
    float* outO = out;
    if (out_size >= 2 * NCHW) {   // output is (R, out) concatenated
        outR = out;
        outO = out + NCHW;
    }

    k_gap<<<4096, 128>>>(R, T, outR);
    k_vecA<<<144, 256>>>(conv_w, bn_g, bn_b, bn_m, bn_v,
                         f1W1, f1b1, f2W1, f2b1);
    k_vecB<<<32, 256>>>(f1W2R, f1b2R, f1W2T, f1b2T,
                        f2W2R, f2b2R, f2W2T, f2b2T);
    k_main<<<NBLK_MAIN, 256>>>(R, T, fv_wR, fv_wT);
    k_wg3<<<8, 256>>>(fv_Lw, fv_Lb, fv_bR, fv_bT);
    k_out<<<512, 256>>>(fv_wO, fv_bO, fv_sR, fv_sT, fv_bR, fv_bT, outO);
}

// round 7
// speedup vs baseline: 1.5166x; 1.1694x over previous
#include <cuda_runtime.h>
#include <cuda_bf16.h>
#include <cuda_pipeline.h>
#include <cstdint>

// Problem constants
#define Nn   8
#define Cc   256
#define Hh   64
#define Ww   64
#define HWp  4096          // H*W
#define Gr   8             // groups
#define KK2  9             // K*K
#define GKK  72            // G*K*K
#define HIDc 256
#define HCc  16
#define NCHW (8*256*4096)
#define CSPLIT 8
#define CPB   (Cc/CSPLIT)            // 32 channels per block (= one filter group)
#define XT    4                      // x tiles of width 16 (full height)
#define NBLK_MAIN (2*Nn*XT*CSPLIT)   // 512

// ---------------- scratch (device globals: no allocation allowed) ----------------
__device__ float  g_gap[2][Nn][Cc];              // per-modality GAP
__device__ float  g_hid[2][Nn][HIDc];            // MLP hidden activations
__device__ float  g_filt[2][Nn][GKK];            // softmaxed dynamic filters
__device__ float2 g_wAB[2][Nn][Cc];              // (wR - wT, wT) gating per channel
__device__ float  g_Fp[2][CSPLIT][Nn][HCc][HWp]; // partial 16-ch features (no bias)
__device__ float  g_bsum[NBLK_MAIN][HCc];        // per-block partial sums for Gf mean
__device__ float  g_wG[Nn][HCc];                 // global gate

// ---------------- Kernel 1: GAP over H,W (+ copy R to output) ----------------
__global__ void k_gap(const float* __restrict__ R, const float* __restrict__ T,
                      float* __restrict__ outR)
{
    int b   = blockIdx.x;          // 0..4095 : mod*2048 + (n*256+c)
    int mod = b >> 11;
    int nc  = b & 2047;
    const float4* p = (const float4*)((mod ? T : R) + (size_t)nc * HWp);
    float4* q = (mod == 0 && outR) ? (float4*)(outR + (size_t)nc * HWp) : nullptr;
    int t = threadIdx.x;           // 128 threads
    float s = 0.f;
#pragma unroll
    for (int i = 0; i < 8; i++) {
        float4 v = p[t + 128 * i];
        if (q) q[t + 128 * i] = v;
        s += v.x + v.y + v.z + v.w;
    }
#pragma unroll
    for (int o = 16; o; o >>= 1) s += __shfl_down_sync(0xffffffffu, s, o);
    __shared__ float sm[4];
    if ((t & 31) == 0) sm[t >> 5] = s;
    __syncthreads();
    if (t == 0)
        g_gap[mod][nc >> 8][nc & 255] = (sm[0] + sm[1] + sm[2] + sm[3]) * (1.f / 4096.f);
}

// ---------------- Kernel 2a: hidden layer + dynamic filters ----------------
__global__ void k_vecA(const float* __restrict__ conv_w,
                       const float* __restrict__ bn_g, const float* __restrict__ bn_b,
                       const float* __restrict__ bn_m, const float* __restrict__ bn_v,
                       const float* __restrict__ f1W1, const float* __restrict__ f1b1,
                       const float* __restrict__ f2W1, const float* __restrict__ f2b1)
{
    int b = blockIdx.x;
    int j = b % 9;
    int n = (b / 9) & 7;
    int mod = b / 72;
    const float* W1 = mod ? f2W1 : f1W1;
    const float* b1 = mod ? f2b1 : f1b1;

    __shared__ float gp[Cc];
    __shared__ float part[8][32];
    __shared__ float lf_sm[GKK];
    int t = threadIdx.x;          // 256
    gp[t] = g_gap[mod][n][t];
    __syncthreads();

    int lane = t & 31, w = t >> 5;
    if (j < 8) {
        int o = j * 32 + lane;
        const float* Wp = W1 + (size_t)(w * 32) * HIDc + o;
        float s = 0.f;
#pragma unroll
        for (int i = 0; i < 32; i++) s += gp[w * 32 + i] * Wp[(size_t)i * HIDc];
        part[w][lane] = s;
        __syncthreads();
        if (t < 32) {
            float a = b1[j * 32 + t];
#pragma unroll
            for (int ww = 0; ww < 8; ww++) a += part[ww][t];
            g_hid[mod][n][j * 32 + t] = fmaxf(a, 0.f);
        }
    } else {
#pragma unroll
        for (int k = 0; k < KK2; k++) {
            int o = w * KK2 + k;
            const float* cw = conv_w + (size_t)o * Cc;
            float a = 0.f;
#pragma unroll
            for (int q = 0; q < 8; q++) a += gp[lane + 32 * q] * cw[lane + 32 * q];
#pragma unroll
            for (int off = 16; off; off >>= 1) a += __shfl_down_sync(0xffffffffu, a, off);
            if (lane == 0)
                lf_sm[o] = (a - bn_m[o]) * rsqrtf(bn_v[o] + 1e-5f) * bn_g[o] + bn_b[o];
        }
        __syncthreads();
        if (t < Gr) {
            float mx = -1e30f;
#pragma unroll
            for (int k = 0; k < KK2; k++) mx = fmaxf(mx, lf_sm[t * KK2 + k]);
            float e[KK2], sum = 0.f;
#pragma unroll
            for (int k = 0; k < KK2; k++) { e[k] = expf(lf_sm[t * KK2 + k] - mx); sum += e[k]; }
            float inv = 1.f / sum;
#pragma unroll
            for (int k = 0; k < KK2; k++) g_filt[mod][n][t * KK2 + k] = e[k] * inv;
        }
    }
}

// ---------------- Kernel 2b: sigmoid gating layers ----------------
__global__ void k_vecB(const float* __restrict__ f1W2R, const float* __restrict__ f1b2R,
                       const float* __restrict__ f1W2T, const float* __restrict__ f1b2T,
                       const float* __restrict__ f2W2R, const float* __restrict__ f2b2R,
                       const float* __restrict__ f2W2T, const float* __restrict__ f2b2T)
{
    int b = blockIdx.x;
    int half = b & 1;
    int n = (b >> 1) & 7;
    int mod = b >> 4;
    const float* W2R = mod ? f2W2R : f1W2R;
    const float* b2R = mod ? f2b2R : f1b2R;
    const float* W2T = mod ? f2W2T : f1W2T;
    const float* b2T = mod ? f2b2T : f1b2T;

    __shared__ float hid_sm[HIDc];
    __shared__ float psR[8][128], psT[8][128];
    int t = threadIdx.x;          // 256
    hid_sm[t] = g_hid[mod][n][t];
    __syncthreads();

    int lane = t & 31, w = t >> 5;
#pragma unroll
    for (int ch = 0; ch < 4; ch++) {
        int o = half * 128 + ch * 32 + lane;
        float aR = 0.f, aT = 0.f;
#pragma unroll
        for (int i2 = 0; i2 < 32; i2++) {
            float h = hid_sm[w * 32 + i2];
            size_t idx = (size_t)(w * 32 + i2) * Cc + o;
            aR += h * W2R[idx];
            aT += h * W2T[idx];
        }
        psR[w][ch * 32 + lane] = aR;
        psT[w][ch * 32 + lane] = aT;
    }
    __syncthreads();
    if (t < 128) {
        int o = half * 128 + t;
        float aR = b2R[o], aT = b2T[o];
#pragma unroll
        for (int ww = 0; ww < 8; ww++) { aR += psR[ww][t]; aT += psT[ww][t]; }
        float wR = 1.f / (1.f + expf(-aR));
        float wT = 1.f / (1.f + expf(-aT));
        g_wAB[mod][n][o] = make_float2(wR - wT, wT);
    }
}

// ---------------- Kernel 3: involution + gating + 256->16 conv ----------------
// grid = 512: ((mod*8 + n)*4 + tile)*8 + cs. Tile = 16 wide x 64 tall stripe,
// 32 channels (one filter group) per block. 256 threads, 4 vertical px/thread.
// cp.async pipeline: 4 channel buffers, 16B interior rows + 4B halo columns.
#define HSTR  20
#define ROWS  66
#define BUFSZ (ROWS * HSTR)
__global__ void __launch_bounds__(256, 2) k_main(const float* __restrict__ R,
                                                 const float* __restrict__ T,
                                                 const float* __restrict__ fv_wR,
                                                 const float* __restrict__ fv_wT)
{
    int b    = blockIdx.x;
    int cs   = b & 7;
    int r    = b >> 3;
    int tile = r & 3;
    r >>= 2;
    int n    = r & 7;
    int mod  = r >> 3;
    int tx0  = tile * 16;

    const float* X    = (mod ? T : R) + (size_t)n * Cc * HWp + (size_t)cs * CPB * HWp;
    const float* wmat = mod ? fv_wT : fv_wR;      // [16][256]
    float* Out = &g_Fp[mod][cs][n][0][0];

    __shared__ float  buf[4][BUFSZ];
    __shared__ float  wv[CPB * HCc];       // transposed: wv[c*16+o], c local
    __shared__ float2 ab_sm[CPB];
    __shared__ float  filt_sm[KK2];
    __shared__ float  red[8][HCc];

    int t = threadIdx.x;
    for (int i = t; i < CPB * HCc; i += 256) {
        int o = i >> 5, c = i & 31;
        wv[c * HCc + o] = wmat[o * Cc + cs * CPB + c];
    }
    if (t < CPB) ab_sm[t] = g_wAB[mod][n][cs * CPB + t];
    if (t < KK2) filt_sm[t] = g_filt[mod][n][cs * KK2 + t];   // group == cs

    // ---- cp.async op tables ----
    // 16B ops: 66 rows x 4 chunks = 264 (thread t does op t; t<8 also op t+256)
    // 4B halo ops: 66 rows x 2 sides = 132 (thread t<132)
    auto refl = [](int gy) { return gy < 0 ? 1 : (gy > 63 ? 62 : gy); };
    int i16a = t;
    int ra = i16a >> 2, sa = i16a & 3;
    int g16a = refl(ra - 1) * Ww + tx0 + sa * 4;
    int s16a = ra * HSTR + sa * 4;
    bool has16b = t < 8;
    int i16b = t + 256;
    int rb = i16b >> 2, sb = i16b & 3;
    int g16b = refl(rb - 1) * Ww + tx0 + sb * 4;
    int s16b = rb * HSTR + sb * 4;
    bool has4 = t < 132;
    int j4 = has4 ? t : 0;
    int rc = j4 >> 1, side = j4 & 1;
    int gx4 = side ? (tx0 + 16 > 63 ? 62 : tx0 + 16) : (tx0 == 0 ? 1 : tx0 - 1);
    int g4 = refl(rc - 1) * Ww + gx4;
    int s4 = rc * HSTR + 16 + side;

    int tx = t & 15, ty = t >> 4;
    int y0 = ty * 4;               // 4 output rows y0..y0+3
    int offL = (tx == 0)  ? 16 : tx - 1;
    int off0 = tx;
    int offR = (tx == 15) ? 17 : tx + 1;

    float acc[4][HCc];
#pragma unroll
    for (int j = 0; j < 4; j++)
#pragma unroll
        for (int i = 0; i < HCc; i++) acc[j][i] = 0.f;

    __syncthreads();               // wv/ab/filt visible
    float f[KK2];
#pragma unroll
    for (int k = 0; k < KK2; k++) f[k] = filt_sm[k];

    // pipeline prologue: channels 0,1,2
#pragma unroll
    for (int p = 0; p < 3; p++) {
        const float* S = X + (size_t)p * HWp;
        float* D = buf[p & 3];
        __pipeline_memcpy_async(&D[s16a], &S[g16a], 16);
        if (has16b) __pipeline_memcpy_async(&D[s16b], &S[g16b], 16);
        if (has4)   __pipeline_memcpy_async(&D[s4],   &S[g4],   4);
        __pipeline_commit();
    }

    for (int c = 0; c < CPB; c++) {
        {   // issue channel c+3
            int q = c + 3;
            if (q < CPB) {
                const float* S = X + (size_t)q * HWp;
                float* D = buf[q & 3];
                __pipeline_memcpy_async(&D[s16a], &S[g16a], 16);
                if (has16b) __pipeline_memcpy_async(&D[s16b], &S[g16b], 16);
                if (has4)   __pipeline_memcpy_async(&D[s4],   &S[g4],   4);
            }
            __pipeline_commit();
        }
        __pipeline_wait_prior(3);
        __syncthreads();

        const float* Bf = buf[c & 3];
        float2 ab = ab_sm[c];
        float Av[6], Bv[6], Cv[6];
#pragma unroll
        for (int rr = 0; rr < 6; rr++) {
            int o = (y0 + rr) * HSTR;
            Av[rr] = Bf[o + offL];
            Bv[rr] = Bf[o + off0];
            Cv[rr] = Bf[o + offR];
        }
        float val[4];
#pragma unroll
        for (int j = 0; j < 4; j++) {
            float low = f[0]*Av[j]   + f[1]*Bv[j]   + f[2]*Cv[j]
                      + f[3]*Av[j+1] + f[4]*Bv[j+1] + f[5]*Cv[j+1]
                      + f[6]*Av[j+2] + f[7]*Bv[j+2] + f[8]*Cv[j+2];
            val[j] = ab.y * Bv[j+1] + ab.x * low;   // wT*X + (wR-wT)*low
        }
        const float4* wp = (const float4*)&wv[c * HCc];
#pragma unroll
        for (int q = 0; q < 4; q++) {
            float4 w = wp[q];
#pragma unroll
            for (int j = 0; j < 4; j++) {
                acc[j][q*4+0] += w.x * val[j];
                acc[j][q*4+1] += w.y * val[j];
                acc[j][q*4+2] += w.z * val[j];
                acc[j][q*4+3] += w.w * val[j];
            }
        }
        __syncthreads();
    }

    // store partial outputs (no bias)
    int x = tx0 + tx;
#pragma unroll
    for (int hc = 0; hc < HCc; hc++)
#pragma unroll
        for (int j = 0; j < 4; j++)
            Out[hc * HWp + (y0 + j) * Ww + x] = acc[j][hc];

    // deterministic per-block reduction for the Gf-mean path
    int lane = t & 31, w = t >> 5;
#pragma unroll
    for (int hc = 0; hc < HCc; hc++) {
        float v = acc[0][hc] + acc[1][hc] + acc[2][hc] + acc[3][hc];
#pragma unroll
        for (int o = 16; o; o >>= 1) v += __shfl_down_sync(0xffffffffu, v, o);
        if (lane == 0) red[w][hc] = v;
    }
    __syncthreads();
    if (t < HCc) {
        float s = 0.f;
#pragma unroll
        for (int ww = 0; ww < 8; ww++) s += red[ww][t];
        g_bsum[blockIdx.x][t] = s;
    }
}

// ---------------- Kernel 4: Gf-mean gate (grid = 8) ----------------
__global__ void k_wg3(const float* __restrict__ Lw, const float* __restrict__ Lb,
                      const float* __restrict__ bR, const float* __restrict__ bT)
{
    int n = blockIdx.x;
    int t = threadIdx.x;          // 256 : slice = t>>4 (16), hc = t&15
    int hc = t & 15, sl = t >> 4;
    __shared__ float red2[16][17];
    __shared__ float mean[HCc];
    float s = 0.f;
#pragma unroll
    for (int k = 0; k < 4; k++) {
        int rr = sl * 4 + k;               // 0..63 : mod*32 + tile*8 + cs
        int idx = ((rr >> 5) * 8 + n) * 32 + (rr & 31);
        s += g_bsum[idx][hc];
    }
    red2[sl][hc] = s;
    __syncthreads();
    if (t < HCc) {
        float a = 0.f;
#pragma unroll
        for (int k = 0; k < 16; k++) a += red2[k][t];
        mean[t] = a * (1.f / 4096.f) + bR[t] + bT[t];
    }
    __syncthreads();
    if (t < HCc) {
        float a = Lb[t];
#pragma unroll
        for (int i = 0; i < HCc; i++) a += mean[i] * Lw[i * HCc + t];
        g_wG[n][t] = 1.f / (1.f + expf(-a));
    }
}

// ---------------- Kernel 5: fovea softmax (over W) + 16->256 conv ----------------
__global__ void __launch_bounds__(256) k_out(const float* __restrict__ wO,
                                             const float* __restrict__ bO,
                                             const float* __restrict__ sRp,
                                             const float* __restrict__ sTp,
                                             const float* __restrict__ bR,
                                             const float* __restrict__ bT,
                                             float* __restrict__ out)
{
    int b = blockIdx.x;            // 512: n*64 + y
    int n = b >> 6, y = b & 63;
    __shared__ float  sR[HCc * Ww], sT[HCc * Ww], fu[HCc * Ww];
    __shared__ float4 wo[Cc * 4];  // wO rows as float4: wo[co*4+q]
    __shared__ float  bo[Cc];
    int t = threadIdx.x;

#pragma unroll
    for (int i = t; i < HCc * Ww; i += 256) {
        int hc = i >> 6, x = i & 63;
        int off = hc * HWp + y * Ww + x;
        float r = bR[hc], tv = bT[hc];
#pragma unroll
        for (int cs = 0; cs < CSPLIT; cs++) {
            r  += g_Fp[0][cs][n][0][off];
            tv += g_Fp[1][cs][n][0][off];
        }
        sR[i] = r;
        sT[i] = tv;
    }
    for (int i = t; i < Cc * 4; i += 256) wo[i] = ((const float4*)wO)[i];
    bo[t] = bO[t];
    float scR = sRp[0], scT = sTp[0];
    __syncthreads();

    int lane = t & 31, w = t >> 5;
#pragma unroll
    for (int hh = 0; hh < 2; hh++) {
        int hc = w + hh * 8;
        float rf0 = sR[hc * Ww + lane], rf1 = sR[hc * Ww + lane + 32];
        float tf0 = sT[hc * Ww + lane], tf1 = sT[hc * Ww + lane + 32];
        float a0 = rf0 * scR, a1 = rf1 * scR;
        float m = fmaxf(a0, a1);
#pragma unroll
        for (int o = 16; o; o >>= 1) m = fmaxf(m, __shfl_xor_sync(0xffffffffu, m, o));
        float e0 = expf(a0 - m), e1 = expf(a1 - m);
        float s = e0 + e1;
#pragma unroll
        for (int o = 16; o; o >>= 1) s += __shfl_xor_sync(0xffffffffu, s, o);
        float inv = 1.f / s;
        float mR0 = e0 * inv, mR1 = e1 * inv;
        float c0 = tf0 * scT, c1 = tf1 * scT;
        float mt = fmaxf(c0, c1);
#pragma unroll
        for (int o = 16; o; o >>= 1) mt = fmaxf(mt, __shfl_xor_sync(0xffffffffu, mt, o));
        float g0 = expf(c0 - mt), g1 = expf(c1 - mt);
        float st = g0 + g1;
#pragma unroll
        for (int o = 16; o; o >>= 1) st += __shfl_xor_sync(0xffffffffu, st, o);
        float invt = 1.f / st;
        float mT0 = g0 * invt, mT1 = g1 * invt;

        float wg = g_wG[n][hc];
        fu[hc * Ww + lane]      = mR0 * rf0 + mT0 * tf0 + wg * (rf0 + tf0);
        fu[hc * Ww + lane + 32] = mR1 * rf1 + mT1 * tf1 + wg * (rf1 + tf1);
    }
    __syncthreads();

    int x = t & 63, co0 = t >> 6;
    float fx[HCc];
#pragma unroll
    for (int i = 0; i < HCc; i++) fx[i] = fu[i * Ww + x];
    float* outp = out + (size_t)n * Cc * HWp + y * Ww + x;
    for (int co = co0; co < Cc; co += 4) {
        const float4* wp = &wo[co * 4];
        float a = bo[co];
#pragma unroll
        for (int q = 0; q < 4; q++) {
            float4 ww = wp[q];
            a += ww.x * fx[q*4+0] + ww.y * fx[q*4+1] + ww.z * fx[q*4+2] + ww.w * fx[q*4+3];
        }
        outp[(size_t)co * HWp] = a;
    }
}

// ---------------- launch ----------------
extern "C" void kernel_launch(void* const* d_in, const int* in_sizes, int n_in,
                              void* d_out, int out_size)
{
    const float* R      = (const float*)d_in[0];
    const float* T      = (const float*)d_in[1];
    const float* conv_w = (const float*)d_in[2];
    const float* bn_g   = (const float*)d_in[3];
    const float* bn_b   = (const float*)d_in[4];
    const float* bn_m   = (const float*)d_in[5];
    const float* bn_v   = (const float*)d_in[6];
    const float* f1W1   = (const float*)d_in[7];
    const float* f1b1   = (const float*)d_in[8];
    const float* f1W2R  = (const float*)d_in[9];
    const float* f1b2R  = (const float*)d_in[10];
    const float* f1W2T  = (const float*)d_in[11];
    const float* f1b2T  = (const float*)d_in[12];
    const float* f2W1   = (const float*)d_in[13];
    const float* f2b1   = (const float*)d_in[14];
    const float* f2W2R  = (const float*)d_in[15];
    const float* f2b2R  = (const float*)d_in[16];
    const float* f2W2T  = (const float*)d_in[17];
    const float* f2b2T  = (const float*)d_in[18];
    const float* fv_wR  = (const float*)d_in[19];
    const float* fv_bR  = (const float*)d_in[20];
    const float* fv_wT  = (const float*)d_in[21];
    const float* fv_bT  = (const float*)d_in[22];
    const float* fv_Lw  = (const float*)d_in[23];
    const float* fv_Lb  = (const float*)d_in[24];
    const float* fv_wO  = (const float*)d_in[25];
    const float* fv_bO  = (const float*)d_in[26];
    const float* fv_sR  = (const float*)d_in[27];
    const float* fv_sT  = (const float*)d_in[28];

    float* out  = (float*)d_out;
    float* outR = nullptr;
    float* outO = out;
    if (out_size >= 2 * NCHW) {   // output is (R, out) concatenated
        outR = out;
        outO = out + NCHW;
    }

    k_gap<<<4096, 128>>>(R, T, outR);
    k_vecA<<<144, 256>>>(conv_w, bn_g, bn_b, bn_m, bn_v,
                         f1W1, f1b1, f2W1, f2b1);
    k_vecB<<<32, 256>>>(f1W2R, f1b2R, f1W2T, f1b2T,
                        f2W2R, f2b2R, f2W2T, f2b2T);
    k_main<<<NBLK_MAIN, 256>>>(R, T, fv_wR, fv_wT);
    k_wg3<<<8, 256>>>(fv_Lw, fv_Lb, fv_bR, fv_bT);
    k_out<<<512, 256>>>(fv_wO, fv_bO, fv_sR, fv_sT, fv_bR, fv_bT, outO);
}

// round 8
// speedup vs baseline: 1.5636x; 1.0310x over previous
#include <cuda_runtime.h>
#include <cuda_bf16.h>
#include <cuda_pipeline.h>
#include <cstdint>

// Problem constants
#define Nn   8
#define Cc   256
#define Hh   64
#define Ww   64
#define HWp  4096          // H*W
#define Gr   8             // groups
#define KK2  9             // K*K
#define GKK  72            // G*K*K
#define HIDc 256
#define HCc  16
#define NCHW (8*256*4096)
#define CSPLIT 8
#define CPB   (Cc/CSPLIT)            // 32 channels per block (= one filter group)
#define XT    4                      // x tiles of width 16 (full height)
#define NBLK_MAIN (2*Nn*XT*CSPLIT)   // 512

// ---------------- packed f32x2 helpers (Blackwell) ----------------
__device__ __forceinline__ unsigned long long pack2(float v) {
    unsigned long long r;
    asm("mov.b64 %0, {%1, %1};" : "=l"(r) : "f"(v));
    return r;
}
__device__ __forceinline__ void fma2(unsigned long long& d,
                                     unsigned long long a, unsigned long long b) {
    asm("fma.rn.f32x2 %0, %1, %2, %0;" : "+l"(d) : "l"(a), "l"(b));
}
__device__ __forceinline__ float2 unpack2(unsigned long long v) {
    float2 r;
    asm("mov.b64 {%0, %1}, %2;" : "=f"(r.x), "=f"(r.y) : "l"(v));
    return r;
}

// ---------------- scratch (device globals: no allocation allowed) ----------------
__device__ float  g_gap[2][Nn][Cc];              // per-modality GAP
__device__ float  g_hid[2][Nn][HIDc];            // MLP hidden activations
__device__ float  g_filt[2][Nn][GKK];            // softmaxed dynamic filters
__device__ float2 g_wAB[2][Nn][Cc];              // (wR - wT, wT) gating per channel
__device__ float  g_Fp[2][CSPLIT][Nn][HCc][HWp]; // partial 16-ch features (no bias)
__device__ float  g_bsum[NBLK_MAIN][HCc];        // per-block partial sums for Gf mean
__device__ float  g_wG[Nn][HCc];                 // global gate

// ---------------- Kernel 1: GAP over H,W (+ copy R to output) ----------------
__global__ void k_gap(const float* __restrict__ R, const float* __restrict__ T,
                      float* __restrict__ outR)
{
    int b   = blockIdx.x;          // 0..4095 : mod*2048 + (n*256+c)
    int mod = b >> 11;
    int nc  = b & 2047;
    const float4* p = (const float4*)((mod ? T : R) + (size_t)nc * HWp);
    float4* q = (mod == 0 && outR) ? (float4*)(outR + (size_t)nc * HWp) : nullptr;
    int t = threadIdx.x;           // 128 threads
    float s = 0.f;
#pragma unroll
    for (int i = 0; i < 8; i++) {
        float4 v = p[t + 128 * i];
        if (q) q[t + 128 * i] = v;
        s += v.x + v.y + v.z + v.w;
    }
#pragma unroll
    for (int o = 16; o; o >>= 1) s += __shfl_down_sync(0xffffffffu, s, o);
    __shared__ float sm[4];
    if ((t & 31) == 0) sm[t >> 5] = s;
    __syncthreads();
    if (t == 0)
        g_gap[mod][nc >> 8][nc & 255] = (sm[0] + sm[1] + sm[2] + sm[3]) * (1.f / 4096.f);
}

// ---------------- Kernel 2a: hidden layer + dynamic filters ----------------
__global__ void k_vecA(const float* __restrict__ conv_w,
                       const float* __restrict__ bn_g, const float* __restrict__ bn_b,
                       const float* __restrict__ bn_m, const float* __restrict__ bn_v,
                       const float* __restrict__ f1W1, const float* __restrict__ f1b1,
                       const float* __restrict__ f2W1, const float* __restrict__ f2b1)
{
    int b = blockIdx.x;
    int j = b % 9;
    int n = (b / 9) & 7;
    int mod = b / 72;
    const float* W1 = mod ? f2W1 : f1W1;
    const float* b1 = mod ? f2b1 : f1b1;

    __shared__ float gp[Cc];
    __shared__ float part[8][32];
    __shared__ float lf_sm[GKK];
    int t = threadIdx.x;          // 256
    gp[t] = g_gap[mod][n][t];
    __syncthreads();

    int lane = t & 31, w = t >> 5;
    if (j < 8) {
        int o = j * 32 + lane;
        const float* Wp = W1 + (size_t)(w * 32) * HIDc + o;
        float s = 0.f;
#pragma unroll
        for (int i = 0; i < 32; i++) s += gp[w * 32 + i] * Wp[(size_t)i * HIDc];
        part[w][lane] = s;
        __syncthreads();
        if (t < 32) {
            float a = b1[j * 32 + t];
#pragma unroll
            for (int ww = 0; ww < 8; ww++) a += part[ww][t];
            g_hid[mod][n][j * 32 + t] = fmaxf(a, 0.f);
        }
    } else {
#pragma unroll
        for (int k = 0; k < KK2; k++) {
            int o = w * KK2 + k;
            const float* cw = conv_w + (size_t)o * Cc;
            float a = 0.f;
#pragma unroll
            for (int q = 0; q < 8; q++) a += gp[lane + 32 * q] * cw[lane + 32 * q];
#pragma unroll
            for (int off = 16; off; off >>= 1) a += __shfl_down_sync(0xffffffffu, a, off);
            if (lane == 0)
                lf_sm[o] = (a - bn_m[o]) * rsqrtf(bn_v[o] + 1e-5f) * bn_g[o] + bn_b[o];
        }
        __syncthreads();
        if (t < Gr) {
            float mx = -1e30f;
#pragma unroll
            for (int k = 0; k < KK2; k++) mx = fmaxf(mx, lf_sm[t * KK2 + k]);
            float e[KK2], sum = 0.f;
#pragma unroll
            for (int k = 0; k < KK2; k++) { e[k] = expf(lf_sm[t * KK2 + k] - mx); sum += e[k]; }
            float inv = 1.f / sum;
#pragma unroll
            for (int k = 0; k < KK2; k++) g_filt[mod][n][t * KK2 + k] = e[k] * inv;
        }
    }
}

// ---------------- Kernel 2b: sigmoid gating layers ----------------
__global__ void k_vecB(const float* __restrict__ f1W2R, const float* __restrict__ f1b2R,
                       const float* __restrict__ f1W2T, const float* __restrict__ f1b2T,
                       const float* __restrict__ f2W2R, const float* __restrict__ f2b2R,
                       const float* __restrict__ f2W2T, const float* __restrict__ f2b2T)
{
    int b = blockIdx.x;
    int half = b & 1;
    int n = (b >> 1) & 7;
    int mod = b >> 4;
    const float* W2R = mod ? f2W2R : f1W2R;
    const float* b2R = mod ? f2b2R : f1b2R;
    const float* W2T = mod ? f2W2T : f1W2T;
    const float* b2T = mod ? f2b2T : f1b2T;

    __shared__ float hid_sm[HIDc];
    __shared__ float psR[8][128], psT[8][128];
    int t = threadIdx.x;          // 256
    hid_sm[t] = g_hid[mod][n][t];
    __syncthreads();

    int lane = t & 31, w = t >> 5;
#pragma unroll
    for (int ch = 0; ch < 4; ch++) {
        int o = half * 128 + ch * 32 + lane;
        float aR = 0.f, aT = 0.f;
#pragma unroll
        for (int i2 = 0; i2 < 32; i2++) {
            float h = hid_sm[w * 32 + i2];
            size_t idx = (size_t)(w * 32 + i2) * Cc + o;
            aR += h * W2R[idx];
            aT += h * W2T[idx];
        }
        psR[w][ch * 32 + lane] = aR;
        psT[w][ch * 32 + lane] = aT;
    }
    __syncthreads();
    if (t < 128) {
        int o = half * 128 + t;
        float aR = b2R[o], aT = b2T[o];
#pragma unroll
        for (int ww = 0; ww < 8; ww++) { aR += psR[ww][t]; aT += psT[ww][t]; }
        float wR = 1.f / (1.f + expf(-aR));
        float wT = 1.f / (1.f + expf(-aT));
        g_wAB[mod][n][o] = make_float2(wR - wT, wT);
    }
}

// ---------------- Kernel 3: involution + gating + 256->16 conv ----------------
// grid = 512: ((mod*8 + n)*4 + tile)*8 + cs. Tile = 16 wide x 64 tall stripe,
// 32 channels (one filter group) per block. 256 threads, 4 vertical px/thread.
// cp.async pipeline: 8 channel buffers (single barrier per channel),
// 16B interior rows + 4B halo columns. Conv-16 done in packed f32x2.
#define HSTR  20
#define ROWS  66
#define BUFSZ (ROWS * HSTR)
__global__ void __launch_bounds__(256, 2) k_main(const float* __restrict__ R,
                                                 const float* __restrict__ T,
                                                 const float* __restrict__ fv_wR,
                                                 const float* __restrict__ fv_wT)
{
    int b    = blockIdx.x;
    int cs   = b & 7;
    int r    = b >> 3;
    int tile = r & 3;
    r >>= 2;
    int n    = r & 7;
    int mod  = r >> 3;
    int tx0  = tile * 16;

    const float* X    = (mod ? T : R) + (size_t)n * Cc * HWp + (size_t)cs * CPB * HWp;
    const float* wmat = mod ? fv_wT : fv_wR;      // [16][256]
    float* Out = &g_Fp[mod][cs][n][0][0];

    __shared__ float  buf[8][BUFSZ];
    __shared__ float  wv[CPB * HCc];       // transposed: wv[c*16+o], c local
    __shared__ float2 ab_sm[CPB];
    __shared__ float  filt_sm[KK2];
    __shared__ float  red[8][HCc];

    int t = threadIdx.x;
    for (int i = t; i < CPB * HCc; i += 256) {
        int o = i >> 5, c = i & 31;
        wv[c * HCc + o] = wmat[o * Cc + cs * CPB + c];
    }
    if (t < CPB) ab_sm[t] = g_wAB[mod][n][cs * CPB + t];
    if (t < KK2) filt_sm[t] = g_filt[mod][n][cs * KK2 + t];   // group == cs

    // ---- cp.async op tables ----
    auto refl = [](int gy) { return gy < 0 ? 1 : (gy > 63 ? 62 : gy); };
    int i16a = t;
    int ra = i16a >> 2, sa = i16a & 3;
    int g16a = refl(ra - 1) * Ww + tx0 + sa * 4;
    int s16a = ra * HSTR + sa * 4;
    bool has16b = t < 8;
    int i16b = t + 256;
    int rb = i16b >> 2, sb = i16b & 3;
    int g16b = refl(rb - 1) * Ww + tx0 + sb * 4;
    int s16b = rb * HSTR + sb * 4;
    bool has4 = t < 132;
    int j4 = has4 ? t : 0;
    int rc = j4 >> 1, side = j4 & 1;
    int gx4 = side ? (tx0 + 16 > 63 ? 62 : tx0 + 16) : (tx0 == 0 ? 1 : tx0 - 1);
    int g4 = refl(rc - 1) * Ww + gx4;
    int s4 = rc * HSTR + 16 + side;

    int tx = t & 15, ty = t >> 4;
    int y0 = ty * 4;               // 4 output rows y0..y0+3
    int offL = (tx == 0)  ? 16 : tx - 1;
    int off0 = tx;
    int offR = (tx == 15) ? 17 : tx + 1;

    unsigned long long accp[4][8];  // f32x2: lanes (hc=2q, hc=2q+1)
#pragma unroll
    for (int j = 0; j < 4; j++)
#pragma unroll
        for (int q = 0; q < 8; q++) accp[j][q] = 0ull;

    __syncthreads();               // wv/ab/filt visible
    float f[KK2];
#pragma unroll
    for (int k = 0; k < KK2; k++) f[k] = filt_sm[k];

    // pipeline prologue: channels 0,1,2
#pragma unroll
    for (int p = 0; p < 3; p++) {
        const float* S = X + (size_t)p * HWp;
        float* D = buf[p];
        __pipeline_memcpy_async(&D[s16a], &S[g16a], 16);
        if (has16b) __pipeline_memcpy_async(&D[s16b], &S[g16b], 16);
        if (has4)   __pipeline_memcpy_async(&D[s4],   &S[g4],   4);
        __pipeline_commit();
    }

    for (int c = 0; c < CPB; c++) {
        {   // issue channel c+3 (writes buf[(c+3)&7]; never read concurrently:
            // slowest thread is in iteration c-1 reading buf[(c-1)&7])
            int q = c + 3;
            if (q < CPB) {
                const float* S = X + (size_t)q * HWp;
                float* D = buf[q & 7];
                __pipeline_memcpy_async(&D[s16a], &S[g16a], 16);
                if (has16b) __pipeline_memcpy_async(&D[s16b], &S[g16b], 16);
                if (has4)   __pipeline_memcpy_async(&D[s4],   &S[g4],   4);
            }
            __pipeline_commit();
        }
        __pipeline_wait_prior(3);
        __syncthreads();           // single barrier per channel

        const float* Bf = buf[c & 7];
        float2 ab = ab_sm[c];
        float Av[6], Bv[6], Cv[6];
#pragma unroll
        for (int rr = 0; rr < 6; rr++) {
            int o = (y0 + rr) * HSTR;
            Av[rr] = Bf[o + offL];
            Bv[rr] = Bf[o + off0];
            Cv[rr] = Bf[o + offR];
        }
        const unsigned long long* wp = (const unsigned long long*)&wv[c * HCc];
        unsigned long long w2[8];
#pragma unroll
        for (int q = 0; q < 8; q++) w2[q] = wp[q];
#pragma unroll
        for (int j = 0; j < 4; j++) {
            float low = f[0]*Av[j]   + f[1]*Bv[j]   + f[2]*Cv[j]
                      + f[3]*Av[j+1] + f[4]*Bv[j+1] + f[5]*Cv[j+1]
                      + f[6]*Av[j+2] + f[7]*Bv[j+2] + f[8]*Cv[j+2];
            float val = ab.y * Bv[j+1] + ab.x * low;   // wT*X + (wR-wT)*low
            unsigned long long v2 = pack2(val);
#pragma unroll
            for (int q = 0; q < 8; q++) fma2(accp[j][q], w2[q], v2);
        }
    }

    // store partial outputs (no bias)
    int x = tx0 + tx;
#pragma unroll
    for (int q = 0; q < 8; q++)
#pragma unroll
        for (int j = 0; j < 4; j++) {
            float2 u = unpack2(accp[j][q]);
            Out[(2 * q)     * HWp + (y0 + j) * Ww + x] = u.x;
            Out[(2 * q + 1) * HWp + (y0 + j) * Ww + x] = u.y;
        }

    // deterministic per-block reduction for the Gf-mean path
    int lane = t & 31, w = t >> 5;
#pragma unroll
    for (int q = 0; q < 8; q++) {
        float2 s0 = unpack2(accp[0][q]), s1 = unpack2(accp[1][q]);
        float2 s2 = unpack2(accp[2][q]), s3 = unpack2(accp[3][q]);
        float vx = s0.x + s1.x + s2.x + s3.x;
        float vy = s0.y + s1.y + s2.y + s3.y;
#pragma unroll
        for (int o = 16; o; o >>= 1) {
            vx += __shfl_down_sync(0xffffffffu, vx, o);
            vy += __shfl_down_sync(0xffffffffu, vy, o);
        }
        if (lane == 0) { red[w][2 * q] = vx; red[w][2 * q + 1] = vy; }
    }
    __syncthreads();
    if (t < HCc) {
        float s = 0.f;
#pragma unroll
        for (int ww = 0; ww < 8; ww++) s += red[ww][t];
        g_bsum[blockIdx.x][t] = s;
    }
}

// ---------------- Kernel 4: Gf-mean gate (grid = 8) ----------------
__global__ void k_wg3(const float* __restrict__ Lw, const float* __restrict__ Lb,
                      const float* __restrict__ bR, const float* __restrict__ bT)
{
    int n = blockIdx.x;
    int t = threadIdx.x;          // 256 : slice = t>>4 (16), hc = t&15
    int hc = t & 15, sl = t >> 4;
    __shared__ float red2[16][17];
    __shared__ float mean[HCc];
    float s = 0.f;
#pragma unroll
    for (int k = 0; k < 4; k++) {
        int rr = sl * 4 + k;               // 0..63 : mod*32 + tile*8 + cs
        int idx = ((rr >> 5) * 8 + n) * 32 + (rr & 31);
        s += g_bsum[idx][hc];
    }
    red2[sl][hc] = s;
    __syncthreads();
    if (t < HCc) {
        float a = 0.f;
#pragma unroll
        for (int k = 0; k < 16; k++) a += red2[k][t];
        mean[t] = a * (1.f / 4096.f) + bR[t] + bT[t];
    }
    __syncthreads();
    if (t < HCc) {
        float a = Lb[t];
#pragma unroll
        for (int i = 0; i < HCc; i++) a += mean[i] * Lw[i * HCc + t];
        g_wG[n][t] = 1.f / (1.f + expf(-a));
    }
}

// ---------------- Kernel 5: fovea softmax (over W) + 16->256 conv ----------------
__global__ void __launch_bounds__(256) k_out(const float* __restrict__ wO,
                                             const float* __restrict__ bO,
                                             const float* __restrict__ sRp,
                                             const float* __restrict__ sTp,
                                             const float* __restrict__ bR,
                                             const float* __restrict__ bT,
                                             float* __restrict__ out)
{
    int b = blockIdx.x;            // 512: n*64 + y
    int n = b >> 6, y = b & 63;
    __shared__ float  sR[HCc * Ww], sT[HCc * Ww], fu[HCc * Ww];
    __shared__ float4 wo[Cc * 4];  // wO rows as float4: wo[co*4+q]
    __shared__ float  bo[Cc];
    int t = threadIdx.x;

#pragma unroll
    for (int i = t; i < HCc * Ww; i += 256) {
        int hc = i >> 6, x = i & 63;
        int off = hc * HWp + y * Ww + x;
        float r = bR[hc], tv = bT[hc];
#pragma unroll
        for (int cs = 0; cs < CSPLIT; cs++) {
            r  += g_Fp[0][cs][n][0][off];
            tv += g_Fp[1][cs][n][0][off];
        }
        sR[i] = r;
        sT[i] = tv;
    }
    for (int i = t; i < Cc * 4; i += 256) wo[i] = ((const float4*)wO)[i];
    bo[t] = bO[t];
    float scR = sRp[0], scT = sTp[0];
    __syncthreads();

    int lane = t & 31, w = t >> 5;
#pragma unroll
    for (int hh = 0; hh < 2; hh++) {
        int hc = w + hh * 8;
        float rf0 = sR[hc * Ww + lane], rf1 = sR[hc * Ww + lane + 32];
        float tf0 = sT[hc * Ww + lane], tf1 = sT[hc * Ww + lane + 32];
        float a0 = rf0 * scR, a1 = rf1 * scR;
        float m = fmaxf(a0, a1);
#pragma unroll
        for (int o = 16; o; o >>= 1) m = fmaxf(m, __shfl_xor_sync(0xffffffffu, m, o));
        float e0 = expf(a0 - m), e1 = expf(a1 - m);
        float s = e0 + e1;
#pragma unroll
        for (int o = 16; o; o >>= 1) s += __shfl_xor_sync(0xffffffffu, s, o);
        float inv = 1.f / s;
        float mR0 = e0 * inv, mR1 = e1 * inv;
        float c0 = tf0 * scT, c1 = tf1 * scT;
        float mt = fmaxf(c0, c1);
#pragma unroll
        for (int o = 16; o; o >>= 1) mt = fmaxf(mt, __shfl_xor_sync(0xffffffffu, mt, o));
        float g0 = expf(c0 - mt), g1 = expf(c1 - mt);
        float st = g0 + g1;
#pragma unroll
        for (int o = 16; o; o >>= 1) st += __shfl_xor_sync(0xffffffffu, st, o);
        float invt = 1.f / st;
        float mT0 = g0 * invt, mT1 = g1 * invt;

        float wg = g_wG[n][hc];
        fu[hc * Ww + lane]      = mR0 * rf0 + mT0 * tf0 + wg * (rf0 + tf0);
        fu[hc * Ww + lane + 32] = mR1 * rf1 + mT1 * tf1 + wg * (rf1 + tf1);
    }
    __syncthreads();

    int x = t & 63, co0 = t >> 6;
    float fx[HCc];
#pragma unroll
    for (int i = 0; i < HCc; i++) fx[i] = fu[i * Ww + x];
    float* outp = out + (size_t)n * Cc * HWp + y * Ww + x;
    for (int co = co0; co < Cc; co += 4) {
        const float4* wp = &wo[co * 4];
        float a = bo[co];
#pragma unroll
        for (int q = 0; q < 4; q++) {
            float4 ww = wp[q];
            a += ww.x * fx[q*4+0] + ww.y * fx[q*4+1] + ww.z * fx[q*4+2] + ww.w * fx[q*4+3];
        }
        outp[(size_t)co * HWp] = a;
    }
}

// ---------------- launch ----------------
extern "C" void kernel_launch(void* const* d_in, const int* in_sizes, int n_in,
                              void* d_out, int out_size)
{
    const float* R      = (const float*)d_in[0];
    const float* T      = (const float*)d_in[1];
    const float* conv_w = (const float*)d_in[2];
    const float* bn_g   = (const float*)d_in[3];
    const float* bn_b   = (const float*)d_in[4];
    const float* bn_m   = (const float*)d_in[5];
    const float* bn_v   = (const float*)d_in[6];
    const float* f1W1   = (const float*)d_in[7];
    const float* f1b1   = (const float*)d_in[8];
    const float* f1W2R  = (const float*)d_in[9];
    const float* f1b2R  = (const float*)d_in[10];
    const float* f1W2T  = (const float*)d_in[11];
    const float* f1b2T  = (const float*)d_in[12];
    const float* f2W1   = (const float*)d_in[13];
    const float* f2b1   = (const float*)d_in[14];
    const float* f2W2R  = (const float*)d_in[15];
    const float* f2b2R  = (const float*)d_in[16];
    const float* f2W2T  = (const float*)d_in[17];
    const float* f2b2T  = (const float*)d_in[18];
    const float* fv_wR  = (const float*)d_in[19];
    const float* fv_bR  = (const float*)d_in[20];
    const float* fv_wT  = (const float*)d_in[21];
    const float* fv_bT  = (const float*)d_in[22];
    const float* fv_Lw  = (const float*)d_in[23];
    const float* fv_Lb  = (const float*)d_in[24];
    const float* fv_wO  = (const float*)d_in[25];
    const float* fv_bO  = (const float*)d_in[26];
    const float* fv_sR  = (const float*)d_in[27];
    const float* fv_sT  = (const float*)d_in[28];

    float* out  = (float*)d_out;
    float* outR = nullptr;
    float* outO = out;
    if (out_size >= 2 * NCHW) {   // output is (R, out) concatenated
        outR = out;
        outO = out + NCHW;
    }

    k_gap<<<4096, 128>>>(R, T, outR);
    k_vecA<<<144, 256>>>(conv_w, bn_g, bn_b, bn_m, bn_v,
                         f1W1, f1b1, f2W1, f2b1);
    k_vecB<<<32, 256>>>(f1W2R, f1b2R, f1W2T, f1b2T,
                        f2W2R, f2b2R, f2W2T, f2b2T);
    k_main<<<NBLK_MAIN, 256>>>(R, T, fv_wR, fv_wT);
    k_wg3<<<8, 256>>>(fv_Lw, fv_Lb, fv_bR, fv_bT);
    k_out<<<512, 256>>>(fv_wO, fv_bO, fv_sR, fv_sT, fv_bR, fv_bT, outO);
}